// round 4
// baseline (speedup 1.0000x reference)
#include <cuda_runtime.h>
#include <math.h>

#define BB 4
#define NN 2048
#define DD 1024
#define HH 8
#define AA 128
#define LV 128
#define NBLK 4
#define MM (BB*NN)          // 8192 rows
#define QKVW 4096
#define QSCALE 0.08838834764831845f   // 1/sqrt(128)
#define INV_N (1.0f/2048.0f)

// ---------------- scratch (device globals; no allocation allowed) ----------
__device__ float g_xn[MM*DD];            // 32 MB
__device__ float g_q [BB*HH*NN*AA];      // 32 MB  (B,H,N,A)
__device__ float g_k [BB*HH*NN*AA];      // 32 MB
__device__ float g_v [BB*HH*NN*LV];      // 32 MB
__device__ float g_attn[MM*DD];          // 32 MB  (B,N,H*Lv)
__device__ float g_mv [BB*HH*LV];        // fallback: column-mean of V per (b,h)

// ---------------- LayerNorm: one row per block, 256 threads ----------------
// FIXED: explicit block reduction with shared-memory BROADCAST (the previous
// helper left lanes 8..31 with 0, inflating output ~316x per layer).
__global__ void ln_kernel(const float* __restrict__ x,
                          const float* __restrict__ g,
                          const float* __restrict__ bta) {
    __shared__ float sh[8];
    __shared__ float bc[2];
    int row = blockIdx.x;
    int tid = threadIdx.x;
    int lane = tid & 31, wid = tid >> 5;

    const float4* xr = (const float4*)(x + (size_t)row * DD);
    float4 v = xr[tid];

    // mean
    float s = v.x + v.y + v.z + v.w;
#pragma unroll
    for (int o = 16; o > 0; o >>= 1) s += __shfl_xor_sync(0xffffffffu, s, o);
    if (lane == 0) sh[wid] = s;
    __syncthreads();
    if (tid == 0) {
        float t = 0.f;
#pragma unroll
        for (int i = 0; i < 8; i++) t += sh[i];
        bc[0] = t;
    }
    __syncthreads();
    float mu = bc[0] * (1.f / DD);

    float dx = v.x - mu, dy = v.y - mu, dz = v.z - mu, dw = v.w - mu;

    // variance
    float sq = dx*dx + dy*dy + dz*dz + dw*dw;
#pragma unroll
    for (int o = 16; o > 0; o >>= 1) sq += __shfl_xor_sync(0xffffffffu, sq, o);
    if (lane == 0) sh[wid] = sq;
    __syncthreads();
    if (tid == 0) {
        float t = 0.f;
#pragma unroll
        for (int i = 0; i < 8; i++) t += sh[i];
        bc[1] = t;
    }
    __syncthreads();
    float rs = rsqrtf(bc[1] * (1.f / DD) + 1e-5f);

    float4 gg = ((const float4*)g)[tid];
    float4 bb = ((const float4*)bta)[tid];
    float4 o;
    o.x = dx * rs * gg.x + bb.x;
    o.y = dy * rs * gg.y + bb.y;
    o.z = dz * rs * gg.z + bb.z;
    o.w = dw * rs * gg.w + bb.w;
    ((float4*)(g_xn + (size_t)row * DD))[tid] = o;
}

// ---------------- QKV GEMM: C[8192,3072] = xn @ W(sel cols) + b -----------
// grid (24, 64): blockIdx.x = 128-wide column chunk -> (head, q/k/v part)
__global__ __launch_bounds__(256) void qkv_gemm(const float* __restrict__ W,
                                                const float* __restrict__ bias) {
    __shared__ float As[8][128];
    __shared__ float Bs[8][128];
    int tid = threadIdx.x;
    int row0 = blockIdx.y * 128;
    int chunk = blockIdx.x;                 // 0..23
    int head = chunk / 3, part = chunk % 3;
    int wcol0 = head * 512 + part * 128;
    float* dst = (part == 0) ? g_q : (part == 1) ? g_k : g_v;

    int aRow = tid >> 1, aCol = (tid & 1) * 4;
    int bRow = tid >> 5, bCol = (tid & 31) * 4;
    int ty = tid >> 4, tx = tid & 15;

    float acc[8][8];
#pragma unroll
    for (int i = 0; i < 8; i++)
#pragma unroll
        for (int j = 0; j < 8; j++) acc[i][j] = 0.f;

    for (int k0 = 0; k0 < DD; k0 += 8) {
        float4 av = *(const float4*)&g_xn[(size_t)(row0 + aRow) * DD + k0 + aCol];
        float4 bv = *(const float4*)&W[(size_t)(k0 + bRow) * QKVW + wcol0 + bCol];
        As[aCol + 0][aRow] = av.x; As[aCol + 1][aRow] = av.y;
        As[aCol + 2][aRow] = av.z; As[aCol + 3][aRow] = av.w;
        *(float4*)&Bs[bRow][bCol] = bv;
        __syncthreads();
#pragma unroll
        for (int kk = 0; kk < 8; kk++) {
            float a[8], b[8];
            *(float4*)&a[0] = *(float4*)&As[kk][ty * 8];
            *(float4*)&a[4] = *(float4*)&As[kk][ty * 8 + 4];
            *(float4*)&b[0] = *(float4*)&Bs[kk][tx * 8];
            *(float4*)&b[4] = *(float4*)&Bs[kk][tx * 8 + 4];
#pragma unroll
            for (int i = 0; i < 8; i++)
#pragma unroll
                for (int j = 0; j < 8; j++) acc[i][j] = fmaf(a[i], b[j], acc[i][j]);
        }
        __syncthreads();
    }
#pragma unroll
    for (int i = 0; i < 8; i++) {
        int r = row0 + ty * 8 + i;
        int b = r >> 11, n = r & (NN - 1);
        float* drow = dst + ((size_t)(b * HH + head) * NN + n) * 128;
#pragma unroll
        for (int j = 0; j < 8; j++) {
            int lane = tx * 8 + j;
            drow[lane] = acc[i][j] + bias[wcol0 + lane];
        }
    }
}

// ---------------- meanV: fallback for fully-masked rows -------------------
__global__ void meanv_kernel() {
    int bh = blockIdx.x;
    int d = threadIdx.x;
    const float* vp = g_v + (size_t)bh * NN * 128 + d;
    float s0 = 0.f, s1 = 0.f, s2 = 0.f, s3 = 0.f;
    for (int m = 0; m < NN; m += 4) {
        s0 += vp[(size_t)(m + 0) * 128];
        s1 += vp[(size_t)(m + 1) * 128];
        s2 += vp[(size_t)(m + 2) * 128];
        s3 += vp[(size_t)(m + 3) * 128];
    }
    g_mv[bh * 128 + d] = (s0 + s1 + s2 + s3) * INV_N;
}

// ---------------- attention: 64-query tile, flash-style online softmax ----
// grid (32, H, B), 256 threads. smem: Qs[128][64] Ks[128][64] Vs[64][128] Ps[64][64]
#define ATTN_SMEM ((3*8192 + 4096) * 4 + 2 * 64 * 4)

__global__ __launch_bounds__(256) void attn_kernel(const int* __restrict__ ids) {
    extern __shared__ float sm[];
    float* Qs = sm;                    // [k][row]
    float* Ks = sm + 128 * 64;         // [k][col]
    float* Vs = sm + 2 * 128 * 64;     // [m][d]
    float* Ps = sm + 3 * 128 * 64;     // [m][row]
    int* vn = (int*)(sm + 3 * 8192 + 4096);
    int* vm = vn + 64;

    int tid = threadIdx.x;
    int n0 = blockIdx.x * 64;
    int h = blockIdx.y;
    int b = blockIdx.z;
    size_t base = (size_t)(b * HH + h) * NN * 128;

    // load Q tile (pre-scaled by 1/sqrt(A)), transposed
    for (int idx = tid; idx < 64 * 32; idx += 256) {
        int r = idx >> 5, c = (idx & 31) * 4;
        float4 qv = *(const float4*)&g_q[base + (size_t)(n0 + r) * 128 + c];
        Qs[(c + 0) * 64 + r] = qv.x * QSCALE;
        Qs[(c + 1) * 64 + r] = qv.y * QSCALE;
        Qs[(c + 2) * 64 + r] = qv.z * QSCALE;
        Qs[(c + 3) * 64 + r] = qv.w * QSCALE;
    }
    if (tid < 64) vn[tid] = (ids[b * NN + n0 + tid] != 0);

    int ty = tid >> 4, tx = tid & 15;
    float run_m[4], run_l[4], acc[4][8];
#pragma unroll
    for (int i = 0; i < 4; i++) {
        run_m[i] = -1e30f; run_l[i] = 0.f;
#pragma unroll
        for (int j = 0; j < 8; j++) acc[i][j] = 0.f;
    }

    // mask is m > n: only tiles with m-range overlapping (n0, N) matter
    for (int mt = (n0 >> 6); mt < NN / 64; ++mt) {
        int m0 = mt * 64;
        __syncthreads();   // previous iter done with Ks/Vs/Ps (also covers Qs fill)
        for (int idx = tid; idx < 64 * 32; idx += 256) {
            int r = idx >> 5, c = (idx & 31) * 4;
            float4 kv = *(const float4*)&g_k[base + (size_t)(m0 + r) * 128 + c];
            Ks[(c + 0) * 64 + r] = kv.x;
            Ks[(c + 1) * 64 + r] = kv.y;
            Ks[(c + 2) * 64 + r] = kv.z;
            Ks[(c + 3) * 64 + r] = kv.w;
            float4 vv = *(const float4*)&g_v[base + (size_t)(m0 + r) * 128 + c];
            *(float4*)&Vs[r * 128 + c] = vv;
        }
        if (tid < 64) vm[tid] = (ids[b * NN + m0 + tid] != 0);
        __syncthreads();

        // S = Q K^T  (4x4 per thread)
        float s[4][4];
#pragma unroll
        for (int i = 0; i < 4; i++)
#pragma unroll
            for (int j = 0; j < 4; j++) s[i][j] = 0.f;
#pragma unroll 8
        for (int kk = 0; kk < 128; kk++) {
            float4 qa = *(float4*)&Qs[kk * 64 + ty * 4];
            float4 kb = *(float4*)&Ks[kk * 64 + tx * 4];
            float a[4] = {qa.x, qa.y, qa.z, qa.w};
            float c2[4] = {kb.x, kb.y, kb.z, kb.w};
#pragma unroll
            for (int i = 0; i < 4; i++)
#pragma unroll
                for (int j = 0; j < 4; j++) s[i][j] = fmaf(a[i], c2[j], s[i][j]);
        }

        // masked silu + online softmax (row group = 16 lanes of same ty)
#pragma unroll
        for (int i = 0; i < 4; i++) {
            int n = n0 + ty * 4 + i;
            int validn = vn[ty * 4 + i];
            float lg[4]; bool cnd[4];
            float tmax = -1e30f;
#pragma unroll
            for (int j = 0; j < 4; j++) {
                int m = m0 + tx * 4 + j;
                bool cc = (m > n) && validn && vm[tx * 4 + j];
                cnd[j] = cc;
                float sc = s[i][j];
                float l = cc ? (sc / (1.f + __expf(-sc))) * INV_N : -1e30f;
                lg[j] = l;
                tmax = fmaxf(tmax, l);
            }
#pragma unroll
            for (int o = 8; o > 0; o >>= 1)
                tmax = fmaxf(tmax, __shfl_xor_sync(0xffffffffu, tmax, o, 16));
            float newm = fmaxf(run_m[i], tmax);
            float resc = __expf(run_m[i] - newm);   // 1 when unchanged; 0 from -1e30
            run_m[i] = newm;
            float p[4]; float psum = 0.f;
#pragma unroll
            for (int j = 0; j < 4; j++) {
                p[j] = cnd[j] ? __expf(lg[j] - newm) : 0.f;
                psum += p[j];
            }
#pragma unroll
            for (int o = 8; o > 0; o >>= 1)
                psum += __shfl_xor_sync(0xffffffffu, psum, o, 16);
            run_l[i] = run_l[i] * resc + psum;
#pragma unroll
            for (int j = 0; j < 8; j++) acc[i][j] *= resc;
#pragma unroll
            for (int j = 0; j < 4; j++) Ps[(tx * 4 + j) * 64 + ty * 4 + i] = p[j];
        }
        __syncthreads();

        // O += P @ V  (4 rows x 8 d-cols per thread)
#pragma unroll 2
        for (int mm = 0; mm < 64; mm++) {
            float4 pa = *(float4*)&Ps[mm * 64 + ty * 4];
            float4 v0 = *(float4*)&Vs[mm * 128 + tx * 8];
            float4 v1 = *(float4*)&Vs[mm * 128 + tx * 8 + 4];
            float pv[4] = {pa.x, pa.y, pa.z, pa.w};
            float vv[8] = {v0.x, v0.y, v0.z, v0.w, v1.x, v1.y, v1.z, v1.w};
#pragma unroll
            for (int i = 0; i < 4; i++)
#pragma unroll
                for (int j = 0; j < 8; j++) acc[i][j] = fmaf(pv[i], vv[j], acc[i][j]);
        }
    }

    // write: normalize, or fall back to uniform-softmax column mean for
    // fully-masked rows (matches reference softmax over all -1e9 logits)
#pragma unroll
    for (int i = 0; i < 4; i++) {
        int n = n0 + ty * 4 + i;
        float* orow = g_attn + ((size_t)(b * NN + n)) * DD + h * 128 + tx * 8;
        float4 o0, o1;
        if (run_l[i] > 0.f) {
            float inv = 1.f / run_l[i];
            o0.x = acc[i][0] * inv; o0.y = acc[i][1] * inv;
            o0.z = acc[i][2] * inv; o0.w = acc[i][3] * inv;
            o1.x = acc[i][4] * inv; o1.y = acc[i][5] * inv;
            o1.z = acc[i][6] * inv; o1.w = acc[i][7] * inv;
        } else {
            const float* mvp = g_mv + (b * HH + h) * 128 + tx * 8;
            o0 = *(const float4*)&mvp[0];
            o1 = *(const float4*)&mvp[4];
        }
        *(float4*)&orow[0] = o0;
        *(float4*)&orow[4] = o1;
    }
}

// ---------------- output GEMM + residual: X += attn @ W + b ---------------
// grid (8, 64)
__global__ __launch_bounds__(256) void out_gemm(const float* __restrict__ W,
                                                const float* __restrict__ bias,
                                                float* __restrict__ X) {
    __shared__ float As[8][128];
    __shared__ float Bs[8][128];
    int tid = threadIdx.x;
    int row0 = blockIdx.y * 128;
    int col0 = blockIdx.x * 128;

    int aRow = tid >> 1, aCol = (tid & 1) * 4;
    int bRow = tid >> 5, bCol = (tid & 31) * 4;
    int ty = tid >> 4, tx = tid & 15;

    float acc[8][8];
#pragma unroll
    for (int i = 0; i < 8; i++)
#pragma unroll
        for (int j = 0; j < 8; j++) acc[i][j] = 0.f;

    for (int k0 = 0; k0 < DD; k0 += 8) {
        float4 av = *(const float4*)&g_attn[(size_t)(row0 + aRow) * DD + k0 + aCol];
        float4 bv = *(const float4*)&W[(size_t)(k0 + bRow) * DD + col0 + bCol];
        As[aCol + 0][aRow] = av.x; As[aCol + 1][aRow] = av.y;
        As[aCol + 2][aRow] = av.z; As[aCol + 3][aRow] = av.w;
        *(float4*)&Bs[bRow][bCol] = bv;
        __syncthreads();
#pragma unroll
        for (int kk = 0; kk < 8; kk++) {
            float a[8], b[8];
            *(float4*)&a[0] = *(float4*)&As[kk][ty * 8];
            *(float4*)&a[4] = *(float4*)&As[kk][ty * 8 + 4];
            *(float4*)&b[0] = *(float4*)&Bs[kk][tx * 8];
            *(float4*)&b[4] = *(float4*)&Bs[kk][tx * 8 + 4];
#pragma unroll
            for (int i = 0; i < 8; i++)
#pragma unroll
                for (int j = 0; j < 8; j++) acc[i][j] = fmaf(a[i], b[j], acc[i][j]);
        }
        __syncthreads();
    }
#pragma unroll
    for (int i = 0; i < 8; i++) {
        size_t r = row0 + ty * 8 + i;
#pragma unroll
        for (int j = 0; j < 8; j++) {
            int col = col0 + tx * 8 + j;
            size_t idx = r * DD + col;
            X[idx] = X[idx] + acc[i][j] + bias[col];
        }
    }
}

// ---------------- launch ----------------
extern "C" void kernel_launch(void* const* d_in, const int* in_sizes, int n_in,
                              void* d_out, int out_size) {
    const int*   ids  = (const int*)d_in[1];     // past_ids (B,N)
    const float* emb  = (const float*)d_in[2];   // past_embeddings (B,N,D)
    const float* qkvw = (const float*)d_in[3];   // (4,1024,4096)
    const float* qkvb = (const float*)d_in[4];   // (4,4096)
    const float* outw = (const float*)d_in[5];   // (4,1024,1024)
    const float* outb = (const float*)d_in[6];   // (4,1024)
    const float* lng  = (const float*)d_in[7];   // (4,1024)
    const float* lnb  = (const float*)d_in[8];   // (4,1024)
    float* X = (float*)d_out;

    cudaFuncSetAttribute(attn_kernel,
                         cudaFuncAttributeMaxDynamicSharedMemorySize, ATTN_SMEM);

    // x = past_embeddings (updated in place across the 4 blocks)
    cudaMemcpyAsync(X, emb, sizeof(float) * (size_t)MM * DD,
                    cudaMemcpyDeviceToDevice);

    for (int l = 0; l < NBLK; l++) {
        ln_kernel<<<MM, 256>>>(X, lng + l * DD, lnb + l * DD);
        qkv_gemm<<<dim3(24, 64), 256>>>(qkvw + (size_t)l * DD * QKVW,
                                        qkvb + (size_t)l * QKVW);
        meanv_kernel<<<BB * HH, 128>>>();
        attn_kernel<<<dim3(NN / 64, HH, BB), 256, ATTN_SMEM>>>(ids);
        out_gemm<<<dim3(8, 64), 256>>>(outw + (size_t)l * DD * DD,
                                       outb + (size_t)l * DD, X);
    }
}

// round 5
// speedup vs baseline: 1.0535x; 1.0535x over previous
#include <cuda_runtime.h>
#include <math.h>

#define BB 4
#define NN 2048
#define DD 1024
#define HH 8
#define AA 128
#define LV 128
#define NBLK 4
#define MM (BB*NN)          // 8192 rows
#define QKVW 4096
#define QSCALE 0.08838834764831845f   // 1/sqrt(128)
#define INV_N (1.0f/2048.0f)

typedef unsigned long long ull;

// ---------------- f32x2 packed-math helpers (Blackwell FFMA2) --------------
__device__ __forceinline__ ull pk2(float lo, float hi) {
    ull r; asm("mov.b64 %0, {%1, %2};" : "=l"(r) : "f"(lo), "f"(hi)); return r;
}
__device__ __forceinline__ float2 upk2(ull p) {
    float2 f; asm("mov.b64 {%0, %1}, %2;" : "=f"(f.x), "=f"(f.y) : "l"(p)); return f;
}
__device__ __forceinline__ ull sw2(ull p) {
    float2 f = upk2(p); return pk2(f.y, f.x);
}
__device__ __forceinline__ void fma2(ull &d, ull a, ull b) {
    asm("fma.rn.f32x2 %0, %1, %2, %0;" : "+l"(d) : "l"(a), "l"(b));
}
__device__ __forceinline__ ull mul2(ull a, ull b) {
    ull d; asm("mul.rn.f32x2 %0, %1, %2;" : "=l"(d) : "l"(a), "l"(b)); return d;
}

// ---------------- scratch (device globals; no allocation allowed) ----------
__device__ float g_xn[MM*DD];            // 32 MB
__device__ float g_q [BB*HH*NN*AA];      // 32 MB  (B,H,N,A)
__device__ float g_k [BB*HH*NN*AA];      // 32 MB
__device__ float g_v [BB*HH*NN*LV];      // 32 MB
__device__ float g_attn[MM*DD];          // 32 MB  (B,N,H*Lv)
__device__ float g_mv [BB*HH*LV];        // fallback: column-mean of V per (b,h)

// ---------------- LayerNorm: one row per block, 256 threads ----------------
__global__ void ln_kernel(const float* __restrict__ x,
                          const float* __restrict__ g,
                          const float* __restrict__ bta) {
    __shared__ float sh[8];
    __shared__ float bc[2];
    int row = blockIdx.x;
    int tid = threadIdx.x;
    int lane = tid & 31, wid = tid >> 5;

    const float4* xr = (const float4*)(x + (size_t)row * DD);
    float4 v = xr[tid];

    float s = v.x + v.y + v.z + v.w;
#pragma unroll
    for (int o = 16; o > 0; o >>= 1) s += __shfl_xor_sync(0xffffffffu, s, o);
    if (lane == 0) sh[wid] = s;
    __syncthreads();
    if (tid == 0) {
        float t = 0.f;
#pragma unroll
        for (int i = 0; i < 8; i++) t += sh[i];
        bc[0] = t;
    }
    __syncthreads();
    float mu = bc[0] * (1.f / DD);

    float dx = v.x - mu, dy = v.y - mu, dz = v.z - mu, dw = v.w - mu;

    float sq = dx*dx + dy*dy + dz*dz + dw*dw;
#pragma unroll
    for (int o = 16; o > 0; o >>= 1) sq += __shfl_xor_sync(0xffffffffu, sq, o);
    if (lane == 0) sh[wid] = sq;
    __syncthreads();
    if (tid == 0) {
        float t = 0.f;
#pragma unroll
        for (int i = 0; i < 8; i++) t += sh[i];
        bc[1] = t;
    }
    __syncthreads();
    float rs = rsqrtf(bc[1] * (1.f / DD) + 1e-5f);

    float4 gg = ((const float4*)g)[tid];
    float4 bb = ((const float4*)bta)[tid];
    float4 o;
    o.x = dx * rs * gg.x + bb.x;
    o.y = dy * rs * gg.y + bb.y;
    o.z = dz * rs * gg.z + bb.z;
    o.w = dw * rs * gg.w + bb.w;
    ((float4*)(g_xn + (size_t)row * DD))[tid] = o;
}

// ---------------- QKV GEMM (f32x2 packed, K-tile 16) ----------------------
// C[8192,3072] = xn @ W(sel cols) + b. grid (24, 64).
__global__ __launch_bounds__(256) void qkv_gemm(const float* __restrict__ W,
                                                const float* __restrict__ bias) {
    __shared__ float As[16][132];      // padded: STS bank = (4k+r)%32, conflict-free
    __shared__ float Bs[16][128];
    int tid = threadIdx.x;
    int row0 = blockIdx.y * 128;
    int chunk = blockIdx.x;                 // 0..23
    int head = chunk / 3, part = chunk % 3;
    int wcol0 = head * 512 + part * 128;
    float* dst = (part == 0) ? g_q : (part == 1) ? g_k : g_v;

    int aRow = tid >> 1, aCol = (tid & 1) * 4;
    int bRow = tid >> 5, bCol = (tid & 31) * 4;
    int ty = tid >> 4, tx = tid & 15;

    ull c1[4][4], c2[4][4];
#pragma unroll
    for (int i = 0; i < 4; i++)
#pragma unroll
        for (int j = 0; j < 4; j++) { c1[i][j] = 0ull; c2[i][j] = 0ull; }

    for (int k0 = 0; k0 < DD; k0 += 16) {
#pragma unroll
        for (int hh = 0; hh < 2; hh++) {
            float4 av = *(const float4*)&g_xn[(size_t)(row0 + aRow) * DD + k0 + aCol + hh * 8];
            As[aCol + hh * 8 + 0][aRow] = av.x;
            As[aCol + hh * 8 + 1][aRow] = av.y;
            As[aCol + hh * 8 + 2][aRow] = av.z;
            As[aCol + hh * 8 + 3][aRow] = av.w;
            float4 bv = *(const float4*)&W[(size_t)(k0 + bRow + hh * 8) * QKVW + wcol0 + bCol];
            *(float4*)&Bs[bRow + hh * 8][bCol] = bv;
        }
        __syncthreads();
#pragma unroll
        for (int kk = 0; kk < 16; kk++) {
            ulonglong2 aA = *(const ulonglong2*)&As[kk][ty * 8];
            ulonglong2 aB = *(const ulonglong2*)&As[kk][ty * 8 + 4];
            ulonglong2 bA = *(const ulonglong2*)&Bs[kk][tx * 8];
            ulonglong2 bB = *(const ulonglong2*)&Bs[kk][tx * 8 + 4];
            ull ap[4] = {aA.x, aA.y, aB.x, aB.y};
            ull bp[4] = {bA.x, bA.y, bB.x, bB.y};
            ull as_[4];
#pragma unroll
            for (int i = 0; i < 4; i++) as_[i] = sw2(ap[i]);
#pragma unroll
            for (int i = 0; i < 4; i++)
#pragma unroll
                for (int j = 0; j < 4; j++) {
                    fma2(c1[i][j], ap[i], bp[j]);
                    fma2(c2[i][j], as_[i], bp[j]);
                }
        }
        __syncthreads();
    }
    // c1[ip][jp]=(C[2i][2j], C[2i+1][2j+1]); c2[ip][jp]=(C[2i+1][2j], C[2i][2j+1])
#pragma unroll
    for (int ip = 0; ip < 4; ip++) {
        int r0 = row0 + ty * 8 + 2 * ip;
        int b0 = r0 >> 11, n0r = r0 & (NN - 1);
        float* drow0 = dst + ((size_t)(b0 * HH + head) * NN + n0r) * 128;
        int r1 = r0 + 1;
        int b1 = r1 >> 11, n1r = r1 & (NN - 1);
        float* drow1 = dst + ((size_t)(b1 * HH + head) * NN + n1r) * 128;
#pragma unroll
        for (int jp = 0; jp < 4; jp++) {
            int lane = tx * 8 + 2 * jp;
            float2 u1 = upk2(c1[ip][jp]);
            float2 u2 = upk2(c2[ip][jp]);
            float bsx = bias[wcol0 + lane], bsy = bias[wcol0 + lane + 1];
            float2 o0 = {u1.x + bsx, u2.y + bsy};
            float2 o1 = {u2.x + bsx, u1.y + bsy};
            *(float2*)&drow0[lane] = o0;
            *(float2*)&drow1[lane] = o1;
        }
    }
}

// ---------------- meanV: fallback for fully-masked rows -------------------
__global__ void meanv_kernel() {
    int bh = blockIdx.x;
    int d = threadIdx.x;
    const float* vp = g_v + (size_t)bh * NN * 128 + d;
    float s0 = 0.f, s1 = 0.f, s2 = 0.f, s3 = 0.f;
    for (int m = 0; m < NN; m += 4) {
        s0 += vp[(size_t)(m + 0) * 128];
        s1 += vp[(size_t)(m + 1) * 128];
        s2 += vp[(size_t)(m + 2) * 128];
        s3 += vp[(size_t)(m + 3) * 128];
    }
    g_mv[bh * 128 + d] = (s0 + s1 + s2 + s3) * INV_N;
}

// ---------------- attention: 64-query tile, flash-style, f32x2 math -------
#define ATTN_SMEM ((3*8192 + 4096) * 4 + 2 * 64 * 4)

__global__ __launch_bounds__(256) void attn_kernel(const int* __restrict__ ids) {
    extern __shared__ float sm[];
    float* Qs = sm;                    // [k][row]
    float* Ks = sm + 128 * 64;         // [k][col]
    float* Vs = sm + 2 * 128 * 64;     // [m][d]
    float* Ps = sm + 3 * 128 * 64;     // [m][row]
    int* vn = (int*)(sm + 3 * 8192 + 4096);
    int* vm = vn + 64;

    int tid = threadIdx.x;
    int n0 = blockIdx.x * 64;
    int h = blockIdx.y;
    int b = blockIdx.z;
    size_t base = (size_t)(b * HH + h) * NN * 128;

    for (int idx = tid; idx < 64 * 32; idx += 256) {
        int r = idx >> 5, c = (idx & 31) * 4;
        float4 qv = *(const float4*)&g_q[base + (size_t)(n0 + r) * 128 + c];
        Qs[(c + 0) * 64 + r] = qv.x * QSCALE;
        Qs[(c + 1) * 64 + r] = qv.y * QSCALE;
        Qs[(c + 2) * 64 + r] = qv.z * QSCALE;
        Qs[(c + 3) * 64 + r] = qv.w * QSCALE;
    }
    if (tid < 64) vn[tid] = (ids[b * NN + n0 + tid] != 0);

    int ty = tid >> 4, tx = tid & 15;
    float run_m[4], run_l[4];
    ull accP1[2][4], accP2[2][4];      // O accumulators, paired along rows
#pragma unroll
    for (int i = 0; i < 4; i++) { run_m[i] = -1e30f; run_l[i] = 0.f; }
#pragma unroll
    for (int ip = 0; ip < 2; ip++)
#pragma unroll
        for (int jp = 0; jp < 4; jp++) { accP1[ip][jp] = 0ull; accP2[ip][jp] = 0ull; }

    for (int mt = (n0 >> 6); mt < NN / 64; ++mt) {
        int m0 = mt * 64;
        __syncthreads();
        for (int idx = tid; idx < 64 * 32; idx += 256) {
            int r = idx >> 5, c = (idx & 31) * 4;
            float4 kv = *(const float4*)&g_k[base + (size_t)(m0 + r) * 128 + c];
            Ks[(c + 0) * 64 + r] = kv.x;
            Ks[(c + 1) * 64 + r] = kv.y;
            Ks[(c + 2) * 64 + r] = kv.z;
            Ks[(c + 3) * 64 + r] = kv.w;
            float4 vv = *(const float4*)&g_v[base + (size_t)(m0 + r) * 128 + c];
            *(float4*)&Vs[r * 128 + c] = vv;
        }
        if (tid < 64) vm[tid] = (ids[b * NN + m0 + tid] != 0);
        __syncthreads();

        // S = Q K^T via f32x2 swap-trick: s1=(a2i b2j, a2i+1 b2j+1), s2=(a2i+1 b2j, a2i b2j+1)
        ull s1p[2][2], s2p[2][2];
#pragma unroll
        for (int i = 0; i < 2; i++)
#pragma unroll
            for (int j = 0; j < 2; j++) { s1p[i][j] = 0ull; s2p[i][j] = 0ull; }
#pragma unroll 4
        for (int kk = 0; kk < 128; kk++) {
            ulonglong2 qa = *(const ulonglong2*)&Qs[kk * 64 + ty * 4];
            ulonglong2 kb = *(const ulonglong2*)&Ks[kk * 64 + tx * 4];
            ull ap0 = qa.x, ap1 = qa.y;
            ull bp0 = kb.x, bp1 = kb.y;
            ull as0 = sw2(ap0), as1 = sw2(ap1);
            fma2(s1p[0][0], ap0, bp0); fma2(s1p[0][1], ap0, bp1);
            fma2(s1p[1][0], ap1, bp0); fma2(s1p[1][1], ap1, bp1);
            fma2(s2p[0][0], as0, bp0); fma2(s2p[0][1], as0, bp1);
            fma2(s2p[1][0], as1, bp0); fma2(s2p[1][1], as1, bp1);
        }
        float s[4][4];
#pragma unroll
        for (int ip = 0; ip < 2; ip++)
#pragma unroll
            for (int jp = 0; jp < 2; jp++) {
                float2 u1 = upk2(s1p[ip][jp]);
                float2 u2 = upk2(s2p[ip][jp]);
                s[2*ip  ][2*jp  ] = u1.x;
                s[2*ip+1][2*jp+1] = u1.y;
                s[2*ip+1][2*jp  ] = u2.x;
                s[2*ip  ][2*jp+1] = u2.y;
            }

        // masked silu + online softmax (row group = 16 lanes of same ty)
        float resc[4];
#pragma unroll
        for (int i = 0; i < 4; i++) {
            int n = n0 + ty * 4 + i;
            int validn = vn[ty * 4 + i];
            float lg[4]; bool cnd[4];
            float tmax = -1e30f;
#pragma unroll
            for (int j = 0; j < 4; j++) {
                int m = m0 + tx * 4 + j;
                bool cc = (m > n) && validn && vm[tx * 4 + j];
                cnd[j] = cc;
                float sc = s[i][j];
                float l = cc ? (sc / (1.f + __expf(-sc))) * INV_N : -1e30f;
                lg[j] = l;
                tmax = fmaxf(tmax, l);
            }
#pragma unroll
            for (int o = 8; o > 0; o >>= 1)
                tmax = fmaxf(tmax, __shfl_xor_sync(0xffffffffu, tmax, o, 16));
            float newm = fmaxf(run_m[i], tmax);
            resc[i] = __expf(run_m[i] - newm);
            run_m[i] = newm;
            float p[4]; float psum = 0.f;
#pragma unroll
            for (int j = 0; j < 4; j++) {
                p[j] = cnd[j] ? __expf(lg[j] - newm) : 0.f;
                psum += p[j];
            }
#pragma unroll
            for (int o = 8; o > 0; o >>= 1)
                psum += __shfl_xor_sync(0xffffffffu, psum, o, 16);
            run_l[i] = run_l[i] * resc[i] + psum;
#pragma unroll
            for (int j = 0; j < 4; j++) Ps[(tx * 4 + j) * 64 + ty * 4 + i] = p[j];
        }
        // rescale O accumulators (packed): P1 rows (2i,2i+1), P2 rows (2i+1,2i)
        {
            ull r1p[2] = {pk2(resc[0], resc[1]), pk2(resc[2], resc[3])};
            ull r2p[2] = {pk2(resc[1], resc[0]), pk2(resc[3], resc[2])};
#pragma unroll
            for (int ip = 0; ip < 2; ip++)
#pragma unroll
                for (int jp = 0; jp < 4; jp++) {
                    accP1[ip][jp] = mul2(accP1[ip][jp], r1p[ip]);
                    accP2[ip][jp] = mul2(accP2[ip][jp], r2p[ip]);
                }
        }
        __syncthreads();

        // O += P @ V  (f32x2 swap-trick)
#pragma unroll 2
        for (int mm = 0; mm < 64; mm++) {
            ulonglong2 pa = *(const ulonglong2*)&Ps[mm * 64 + ty * 4];
            ulonglong2 v0 = *(const ulonglong2*)&Vs[mm * 128 + tx * 8];
            ulonglong2 v1 = *(const ulonglong2*)&Vs[mm * 128 + tx * 8 + 4];
            ull pp0 = pa.x, pp1 = pa.y;
            ull ps0 = sw2(pp0), ps1 = sw2(pp1);
            ull vp[4] = {v0.x, v0.y, v1.x, v1.y};
#pragma unroll
            for (int jp = 0; jp < 4; jp++) {
                fma2(accP1[0][jp], pp0, vp[jp]);
                fma2(accP2[0][jp], ps0, vp[jp]);
                fma2(accP1[1][jp], pp1, vp[jp]);
                fma2(accP2[1][jp], ps1, vp[jp]);
            }
        }
    }

    // unpack O: P1[ip][jp]=(O[2i][2j],O[2i+1][2j+1]); P2=(O[2i+1][2j],O[2i][2j+1])
    float oacc[4][8];
#pragma unroll
    for (int ip = 0; ip < 2; ip++)
#pragma unroll
        for (int jp = 0; jp < 4; jp++) {
            float2 u1 = upk2(accP1[ip][jp]);
            float2 u2 = upk2(accP2[ip][jp]);
            oacc[2*ip  ][2*jp  ] = u1.x;
            oacc[2*ip+1][2*jp+1] = u1.y;
            oacc[2*ip+1][2*jp  ] = u2.x;
            oacc[2*ip  ][2*jp+1] = u2.y;
        }

#pragma unroll
    for (int i = 0; i < 4; i++) {
        int n = n0 + ty * 4 + i;
        float* orow = g_attn + ((size_t)(b * NN + n)) * DD + h * 128 + tx * 8;
        float4 o0, o1;
        if (run_l[i] > 0.f) {
            float inv = 1.f / run_l[i];
            o0.x = oacc[i][0] * inv; o0.y = oacc[i][1] * inv;
            o0.z = oacc[i][2] * inv; o0.w = oacc[i][3] * inv;
            o1.x = oacc[i][4] * inv; o1.y = oacc[i][5] * inv;
            o1.z = oacc[i][6] * inv; o1.w = oacc[i][7] * inv;
        } else {
            const float* mvp = g_mv + (b * HH + h) * 128 + tx * 8;
            o0 = *(const float4*)&mvp[0];
            o1 = *(const float4*)&mvp[4];
        }
        *(float4*)&orow[0] = o0;
        *(float4*)&orow[4] = o1;
    }
}

// ---------------- output GEMM + residual (f32x2, K-tile 16) ---------------
// grid (8, 64)
__global__ __launch_bounds__(256) void out_gemm(const float* __restrict__ W,
                                                const float* __restrict__ bias,
                                                float* __restrict__ X) {
    __shared__ float As[16][132];
    __shared__ float Bs[16][128];
    int tid = threadIdx.x;
    int row0 = blockIdx.y * 128;
    int col0 = blockIdx.x * 128;

    int aRow = tid >> 1, aCol = (tid & 1) * 4;
    int bRow = tid >> 5, bCol = (tid & 31) * 4;
    int ty = tid >> 4, tx = tid & 15;

    ull c1[4][4], c2[4][4];
#pragma unroll
    for (int i = 0; i < 4; i++)
#pragma unroll
        for (int j = 0; j < 4; j++) { c1[i][j] = 0ull; c2[i][j] = 0ull; }

    for (int k0 = 0; k0 < DD; k0 += 16) {
#pragma unroll
        for (int hh = 0; hh < 2; hh++) {
            float4 av = *(const float4*)&g_attn[(size_t)(row0 + aRow) * DD + k0 + aCol + hh * 8];
            As[aCol + hh * 8 + 0][aRow] = av.x;
            As[aCol + hh * 8 + 1][aRow] = av.y;
            As[aCol + hh * 8 + 2][aRow] = av.z;
            As[aCol + hh * 8 + 3][aRow] = av.w;
            float4 bv = *(const float4*)&W[(size_t)(k0 + bRow + hh * 8) * DD + col0 + bCol];
            *(float4*)&Bs[bRow + hh * 8][bCol] = bv;
        }
        __syncthreads();
#pragma unroll
        for (int kk = 0; kk < 16; kk++) {
            ulonglong2 aA = *(const ulonglong2*)&As[kk][ty * 8];
            ulonglong2 aB = *(const ulonglong2*)&As[kk][ty * 8 + 4];
            ulonglong2 bA = *(const ulonglong2*)&Bs[kk][tx * 8];
            ulonglong2 bB = *(const ulonglong2*)&Bs[kk][tx * 8 + 4];
            ull ap[4] = {aA.x, aA.y, aB.x, aB.y};
            ull bp[4] = {bA.x, bA.y, bB.x, bB.y};
            ull as_[4];
#pragma unroll
            for (int i = 0; i < 4; i++) as_[i] = sw2(ap[i]);
#pragma unroll
            for (int i = 0; i < 4; i++)
#pragma unroll
                for (int j = 0; j < 4; j++) {
                    fma2(c1[i][j], ap[i], bp[j]);
                    fma2(c2[i][j], as_[i], bp[j]);
                }
        }
        __syncthreads();
    }
#pragma unroll
    for (int ip = 0; ip < 4; ip++) {
        size_t r0 = row0 + ty * 8 + 2 * ip;
        size_t r1 = r0 + 1;
#pragma unroll
        for (int jp = 0; jp < 4; jp++) {
            int col = col0 + tx * 8 + 2 * jp;
            float2 u1 = upk2(c1[ip][jp]);
            float2 u2 = upk2(c2[ip][jp]);
            float bsx = bias[col], bsy = bias[col + 1];
            float2 x0 = *(float2*)&X[r0 * DD + col];
            float2 x1 = *(float2*)&X[r1 * DD + col];
            x0.x += u1.x + bsx;  x0.y += u2.y + bsy;
            x1.x += u2.x + bsx;  x1.y += u1.y + bsy;
            *(float2*)&X[r0 * DD + col] = x0;
            *(float2*)&X[r1 * DD + col] = x1;
        }
    }
}

// ---------------- launch ----------------
extern "C" void kernel_launch(void* const* d_in, const int* in_sizes, int n_in,
                              void* d_out, int out_size) {
    const int*   ids  = (const int*)d_in[1];     // past_ids (B,N)
    const float* emb  = (const float*)d_in[2];   // past_embeddings (B,N,D)
    const float* qkvw = (const float*)d_in[3];   // (4,1024,4096)
    const float* qkvb = (const float*)d_in[4];   // (4,4096)
    const float* outw = (const float*)d_in[5];   // (4,1024,1024)
    const float* outb = (const float*)d_in[6];   // (4,1024)
    const float* lng  = (const float*)d_in[7];   // (4,1024)
    const float* lnb  = (const float*)d_in[8];   // (4,1024)
    float* X = (float*)d_out;

    cudaFuncSetAttribute(attn_kernel,
                         cudaFuncAttributeMaxDynamicSharedMemorySize, ATTN_SMEM);

    cudaMemcpyAsync(X, emb, sizeof(float) * (size_t)MM * DD,
                    cudaMemcpyDeviceToDevice);

    for (int l = 0; l < NBLK; l++) {
        ln_kernel<<<MM, 256>>>(X, lng + l * DD, lnb + l * DD);
        qkv_gemm<<<dim3(24, 64), 256>>>(qkvw + (size_t)l * DD * QKVW,
                                        qkvb + (size_t)l * QKVW);
        meanv_kernel<<<BB * HH, 128>>>();
        attn_kernel<<<dim3(NN / 64, HH, BB), 256, ATTN_SMEM>>>(ids);
        out_gemm<<<dim3(8, 64), 256>>>(outw + (size_t)l * DD * DD,
                                       outb + (size_t)l * DD, X);
    }
}

// round 8
// speedup vs baseline: 1.4608x; 1.3865x over previous
#include <cuda_runtime.h>
#include <cuda_bf16.h>
#include <math.h>
#include <stdint.h>

#define BB 4
#define NN 2048
#define DD 1024
#define HH 8
#define AA 128
#define LV 128
#define NBLK 4
#define MM (BB*NN)          // 8192 rows
#define QKVW 4096
#define QSCALE 0.08838834764831845f   // 1/sqrt(128)
#define INV_N (1.0f/2048.0f)

typedef unsigned long long ull;
typedef __nv_bfloat16 bf16;

// ---------------- scratch (device globals; no allocation allowed) ----------
__device__ bf16  g_xnh[MM*DD];           // 16 MB  ln output hi
__device__ bf16  g_xnl[MM*DD];           // 16 MB  ln output lo
__device__ float g_q [BB*HH*NN*AA];      // 32 MB  (B,H,N,A)
__device__ float g_k [BB*HH*NN*AA];      // 32 MB
__device__ float g_v [BB*HH*NN*LV];      // 32 MB
__device__ bf16  g_ath[MM*DD];           // 16 MB  attn output hi
__device__ bf16  g_atl[MM*DD];           // 16 MB  attn output lo
__device__ float g_mv [BB*HH*LV];        // fallback: column-mean of V per (b,h)
__device__ bf16  g_wqh[(size_t)NBLK*3072*DD];  // qkv W^T hi  [l][n(3072)][k(1024)]
__device__ bf16  g_wql[(size_t)NBLK*3072*DD];
__device__ bf16  g_w2h[(size_t)NBLK*DD*DD];    // out W^T hi  [l][n(1024)][k(1024)]
__device__ bf16  g_w2l[(size_t)NBLK*DD*DD];

// ---------------- small helpers ----------------
__device__ __forceinline__ void split2(float x, bf16 &h, bf16 &l) {
    h = __float2bfloat16(x);
    l = __float2bfloat16(x - __bfloat162float(h));
}
__device__ __forceinline__ unsigned short us(bf16 h) { return __bfloat16_as_ushort(h); }

// ---------------- f32x2 packed-math helpers (attention uses these) ---------
__device__ __forceinline__ ull pk2(float lo, float hi) {
    ull r; asm("mov.b64 %0, {%1, %2};" : "=l"(r) : "f"(lo), "f"(hi)); return r;
}
__device__ __forceinline__ float2 upk2(ull p) {
    float2 f; asm("mov.b64 {%0, %1}, %2;" : "=f"(f.x), "=f"(f.y) : "l"(p)); return f;
}
__device__ __forceinline__ ull sw2(ull p) {
    float2 f = upk2(p); return pk2(f.y, f.x);
}
__device__ __forceinline__ void fma2(ull &d, ull a, ull b) {
    asm("fma.rn.f32x2 %0, %1, %2, %0;" : "+l"(d) : "l"(a), "l"(b));
}
__device__ __forceinline__ ull mul2(ull a, ull b) {
    ull d; asm("mul.rn.f32x2 %0, %1, %2;" : "=l"(d) : "l"(a), "l"(b)); return d;
}

// ---------------- HMMA path: mma.sync + ldmatrix + cp.async ---------------
__device__ __forceinline__ uint32_t smem_u32(const void* p) {
    uint32_t a;
    asm("{ .reg .u64 t; cvta.to.shared.u64 t, %1; cvt.u32.u64 %0, t; }"
        : "=r"(a) : "l"(p));
    return a;
}
__device__ __forceinline__ void mma_bf16(float* c, const uint32_t* a, const uint32_t* b) {
    asm volatile(
        "mma.sync.aligned.m16n8k16.row.col.f32.bf16.bf16.f32 "
        "{%0,%1,%2,%3}, {%4,%5,%6,%7}, {%8,%9}, {%0,%1,%2,%3};"
        : "+f"(c[0]), "+f"(c[1]), "+f"(c[2]), "+f"(c[3])
        : "r"(a[0]), "r"(a[1]), "r"(a[2]), "r"(a[3]), "r"(b[0]), "r"(b[1]));
}
__device__ __forceinline__ void ldsm4(uint32_t* r, uint32_t addr) {
    asm volatile("ldmatrix.sync.aligned.m8n8.x4.shared.b16 {%0,%1,%2,%3}, [%4];"
                 : "=r"(r[0]), "=r"(r[1]), "=r"(r[2]), "=r"(r[3]) : "r"(addr));
}
__device__ __forceinline__ void cpa16(uint32_t dst, const void* src) {
    asm volatile("cp.async.ca.shared.global [%0], [%1], 16;"
                 :: "r"(dst), "l"(src) : "memory");
}
#define CPA_COMMIT asm volatile("cp.async.commit_group;" ::: "memory")
#define CPA_WAIT1  asm volatile("cp.async.wait_group 1;" ::: "memory")
#define CPA_WAIT0  asm volatile("cp.async.wait_group 0;" ::: "memory")

// ---------------- LayerNorm: one row per block, emits bf16 hi/lo ----------
__global__ void ln_kernel(const float* __restrict__ x,
                          const float* __restrict__ g,
                          const float* __restrict__ bta) {
    __shared__ float sh[8];
    __shared__ float bc[2];
    int row = blockIdx.x;
    int tid = threadIdx.x;
    int lane = tid & 31, wid = tid >> 5;

    const float4* xr = (const float4*)(x + (size_t)row * DD);
    float4 v = xr[tid];

    float s = v.x + v.y + v.z + v.w;
#pragma unroll
    for (int o = 16; o > 0; o >>= 1) s += __shfl_xor_sync(0xffffffffu, s, o);
    if (lane == 0) sh[wid] = s;
    __syncthreads();
    if (tid == 0) {
        float t = 0.f;
#pragma unroll
        for (int i = 0; i < 8; i++) t += sh[i];
        bc[0] = t;
    }
    __syncthreads();
    float mu = bc[0] * (1.f / DD);

    float dx = v.x - mu, dy = v.y - mu, dz = v.z - mu, dw = v.w - mu;

    float sq = dx*dx + dy*dy + dz*dz + dw*dw;
#pragma unroll
    for (int o = 16; o > 0; o >>= 1) sq += __shfl_xor_sync(0xffffffffu, sq, o);
    if (lane == 0) sh[wid] = sq;
    __syncthreads();
    if (tid == 0) {
        float t = 0.f;
#pragma unroll
        for (int i = 0; i < 8; i++) t += sh[i];
        bc[1] = t;
    }
    __syncthreads();
    float rs = rsqrtf(bc[1] * (1.f / DD) + 1e-5f);

    float4 gg = ((const float4*)g)[tid];
    float4 bb = ((const float4*)bta)[tid];
    float o0 = dx * rs * gg.x + bb.x;
    float o1 = dy * rs * gg.y + bb.y;
    float o2 = dz * rs * gg.z + bb.z;
    float o3 = dw * rs * gg.w + bb.w;

    bf16 h0, h1, h2, h3, l0, l1, l2, l3;
    split2(o0, h0, l0); split2(o1, h1, l1);
    split2(o2, h2, l2); split2(o3, h3, l3);
    size_t o = (size_t)row * DD + tid * 4;
    ushort4 hv = {us(h0), us(h1), us(h2), us(h3)};
    ushort4 lv = {us(l0), us(l1), us(l2), us(l3)};
    *(ushort4*)&g_xnh[o] = hv;
    *(ushort4*)&g_xnl[o] = lv;
}

// ---------------- weight transpose + split (once per launch) ---------------
__global__ void wq_cvt(const float* __restrict__ qkvw) {
    __shared__ float t[32][33];
    int l = blockIdx.z;
    int k0 = blockIdx.x * 32, n0 = blockIdx.y * 32;
    int chunk = n0 >> 7, head = chunk / 3, part = chunk % 3;
    int wbase = head * 512 + part * 128 + (n0 & 127);
    const float* W = qkvw + (size_t)l * DD * QKVW;
#pragma unroll
    for (int s = 0; s < 4; s++)
        t[threadIdx.y + 8*s][threadIdx.x] =
            W[(size_t)(k0 + threadIdx.y + 8*s) * QKVW + wbase + threadIdx.x];
    __syncthreads();
#pragma unroll
    for (int s = 0; s < 4; s++) {
        int n = n0 + threadIdx.y + 8*s;
        float v = t[threadIdx.x][threadIdx.y + 8*s];
        bf16 h, lo; split2(v, h, lo);
        size_t o = ((size_t)l * 3072 + n) * DD + k0 + threadIdx.x;
        g_wqh[o] = h; g_wql[o] = lo;
    }
}
__global__ void w2_cvt(const float* __restrict__ outw) {
    __shared__ float t[32][33];
    int l = blockIdx.z;
    int k0 = blockIdx.x * 32, n0 = blockIdx.y * 32;
    const float* W = outw + (size_t)l * DD * DD;
#pragma unroll
    for (int s = 0; s < 4; s++)
        t[threadIdx.y + 8*s][threadIdx.x] =
            W[(size_t)(k0 + threadIdx.y + 8*s) * DD + n0 + threadIdx.x];
    __syncthreads();
#pragma unroll
    for (int s = 0; s < 4; s++) {
        int n = n0 + threadIdx.y + 8*s;
        float v = t[threadIdx.x][threadIdx.y + 8*s];
        bf16 h, lo; split2(v, h, lo);
        size_t o = ((size_t)l * DD + n) * DD + k0 + threadIdx.x;
        g_w2h[o] = h; g_w2l[o] = lo;
    }
}

// ---------------- HMMA GEMM: 128x128 tile, BK=32, split-bf16 (3 MMAs) -----
// mode 0: C = xn @ Wqkv + bias, scatter to q/k/v    (grid (24, 64))
// mode 1: X += attn @ Wout + bias                   (grid (8, 64))
// smem stage: Ah[128][40] Al Bh[128][40] Bl (bf16, 80B rows), 2 stages.
#define RSTR 80
#define ST_A_H 0
#define ST_A_L 10240
#define ST_B_H 20480
#define ST_B_L 30720
#define STAGE  40960
#define HM_SMEM (2*STAGE)

__global__ __launch_bounds__(256) void hmma_gemm(int mode, int layer,
                                                 const float* __restrict__ bias,
                                                 float* __restrict__ X) {
    extern __shared__ char smem[];
    uint32_t sb = smem_u32(smem);
    int tid = threadIdx.x;
    int w = tid >> 5, lane = tid & 31;
    int row0 = blockIdx.y * 128;
    int bx = blockIdx.x;

    const bf16* Ah = ((mode == 0) ? g_xnh : g_ath) + (size_t)row0 * DD;
    const bf16* Al = ((mode == 0) ? g_xnl : g_atl) + (size_t)row0 * DD;
    const bf16* Bh = ((mode == 0) ? (g_wqh + (size_t)layer * 3072 * DD)
                                  : (g_w2h + (size_t)layer * DD * DD))
                     + (size_t)(bx * 128) * DD;
    const bf16* Bl = ((mode == 0) ? (g_wql + (size_t)layer * 3072 * DD)
                                  : (g_w2l + (size_t)layer * DD * DD))
                     + (size_t)(bx * 128) * DD;

    float c[4][4][4];
#pragma unroll
    for (int i = 0; i < 4; i++)
#pragma unroll
        for (int j = 0; j < 4; j++)
#pragma unroll
            for (int q = 0; q < 4; q++) c[i][j][q] = 0.f;

    int wm = w & 1, wn = w >> 1;
    int grp = lane >> 3, r8 = lane & 7;
    int arow = wm * 64 + (grp & 1) * 8 + r8;
    int akb0 = (grp >> 1) * 16;
    int brow = wn * 32 + (grp >> 1) * 8 + r8;
    int bkb0 = (grp & 1) * 16;

    // prologue: stage 0
    {
        uint32_t s0 = sb;
#pragma unroll
        for (int ch = tid; ch < 512; ch += 256) {
            int row = ch >> 2, cw = ch & 3;
            uint32_t so = row * RSTR + cw * 16;
            size_t go = (size_t)row * DD + cw * 8;
            cpa16(s0 + ST_A_H + so, (const char*)(Ah + go));
            cpa16(s0 + ST_A_L + so, (const char*)(Al + go));
            cpa16(s0 + ST_B_H + so, (const char*)(Bh + go));
            cpa16(s0 + ST_B_L + so, (const char*)(Bl + go));
        }
        CPA_COMMIT;
    }

    for (int s = 0; s < 32; s++) {
        if (s + 1 < 32) {
            uint32_t s0 = sb + ((s + 1) & 1) * STAGE;
            int k0 = (s + 1) * 32;
#pragma unroll
            for (int ch = tid; ch < 512; ch += 256) {
                int row = ch >> 2, cw = ch & 3;
                uint32_t so = row * RSTR + cw * 16;
                size_t go = (size_t)row * DD + k0 + cw * 8;
                cpa16(s0 + ST_A_H + so, (const char*)(Ah + go));
                cpa16(s0 + ST_A_L + so, (const char*)(Al + go));
                cpa16(s0 + ST_B_H + so, (const char*)(Bh + go));
                cpa16(s0 + ST_B_L + so, (const char*)(Bl + go));
            }
        }
        CPA_COMMIT;
        CPA_WAIT1;
        __syncthreads();
        uint32_t base = sb + (s & 1) * STAGE;
#pragma unroll
        for (int k16 = 0; k16 < 2; k16++) {
            uint32_t ah[4][4], al[4][4], bh[2][4], bl[2][4];
            int akb = k16 * 32 + akb0;
            int bkb = k16 * 32 + bkb0;
#pragma unroll
            for (int i = 0; i < 4; i++) {
                uint32_t ao = (uint32_t)(arow + i * 16) * RSTR + akb;
                ldsm4(ah[i], base + ST_A_H + ao);
                ldsm4(al[i], base + ST_A_L + ao);
            }
#pragma unroll
            for (int j = 0; j < 2; j++) {
                uint32_t bo = (uint32_t)(brow + j * 16) * RSTR + bkb;
                ldsm4(bh[j], base + ST_B_H + bo);
                ldsm4(bl[j], base + ST_B_L + bo);
            }
#pragma unroll
            for (int i = 0; i < 4; i++)
#pragma unroll
                for (int jn = 0; jn < 4; jn++) {
                    const uint32_t* bph = &bh[jn >> 1][(jn & 1) * 2];
                    const uint32_t* bpl = &bl[jn >> 1][(jn & 1) * 2];
                    mma_bf16(c[i][jn], ah[i], bph);
                    mma_bf16(c[i][jn], ah[i], bpl);
                    mma_bf16(c[i][jn], al[i], bph);
                }
        }
        __syncthreads();
    }
    CPA_WAIT0;

    // epilogue
    int quad = lane >> 2, tq = lane & 3;
    if (mode == 0) {
        int head = bx / 3, part = bx % 3;
        int wcol0 = head * 512 + part * 128;
        float* dst = (part == 0) ? g_q : (part == 1) ? g_k : g_v;
#pragma unroll
        for (int i = 0; i < 4; i++)
#pragma unroll
            for (int half = 0; half < 2; half++) {
                int r = row0 + wm * 64 + i * 16 + quad + half * 8;
                int b = r >> 11, n = r & (NN - 1);
                float* drow = dst + ((size_t)(b * HH + head) * NN + n) * 128;
#pragma unroll
                for (int jn = 0; jn < 4; jn++) {
                    int col = wn * 32 + jn * 8 + tq * 2;
                    float2 o;
                    o.x = c[i][jn][half * 2 + 0] + bias[wcol0 + col];
                    o.y = c[i][jn][half * 2 + 1] + bias[wcol0 + col + 1];
                    *(float2*)&drow[col] = o;
                }
            }
    } else {
        int col0 = bx * 128;
#pragma unroll
        for (int i = 0; i < 4; i++)
#pragma unroll
            for (int half = 0; half < 2; half++) {
                size_t r = row0 + wm * 64 + i * 16 + quad + half * 8;
#pragma unroll
                for (int jn = 0; jn < 4; jn++) {
                    int col = col0 + wn * 32 + jn * 8 + tq * 2;
                    float2 x = *(float2*)&X[r * DD + col];
                    x.x += c[i][jn][half * 2 + 0] + bias[col];
                    x.y += c[i][jn][half * 2 + 1] + bias[col + 1];
                    *(float2*)&X[r * DD + col] = x;
                }
            }
    }
}

// ---------------- meanV: fallback for fully-masked rows -------------------
__global__ void meanv_kernel() {
    int bh = blockIdx.x;
    int d = threadIdx.x;
    const float* vp = g_v + (size_t)bh * NN * 128 + d;
    float s0 = 0.f, s1 = 0.f, s2 = 0.f, s3 = 0.f;
    for (int m = 0; m < NN; m += 4) {
        s0 += vp[(size_t)(m + 0) * 128];
        s1 += vp[(size_t)(m + 1) * 128];
        s2 += vp[(size_t)(m + 2) * 128];
        s3 += vp[(size_t)(m + 3) * 128];
    }
    g_mv[bh * 128 + d] = (s0 + s1 + s2 + s3) * INV_N;
}

// ---------------- attention: 64-query tile, flash-style, f32x2 math -------
#define ATTN_SMEM ((3*8192 + 4096) * 4 + 2 * 64 * 4)

__global__ __launch_bounds__(256) void attn_kernel(const int* __restrict__ ids) {
    extern __shared__ float sm[];
    float* Qs = sm;                    // [k][row]
    float* Ks = sm + 128 * 64;         // [k][col]
    float* Vs = sm + 2 * 128 * 64;     // [m][d]
    float* Ps = sm + 3 * 128 * 64;     // [m][row]
    int* vn = (int*)(sm + 3 * 8192 + 4096);
    int* vm = vn + 64;

    int tid = threadIdx.x;
    int n0 = blockIdx.x * 64;
    int h = blockIdx.y;
    int b = blockIdx.z;
    size_t base = (size_t)(b * HH + h) * NN * 128;

    for (int idx = tid; idx < 64 * 32; idx += 256) {
        int r = idx >> 5, c = (idx & 31) * 4;
        float4 qv = *(const float4*)&g_q[base + (size_t)(n0 + r) * 128 + c];
        Qs[(c + 0) * 64 + r] = qv.x * QSCALE;
        Qs[(c + 1) * 64 + r] = qv.y * QSCALE;
        Qs[(c + 2) * 64 + r] = qv.z * QSCALE;
        Qs[(c + 3) * 64 + r] = qv.w * QSCALE;
    }
    if (tid < 64) vn[tid] = (ids[b * NN + n0 + tid] != 0);

    int ty = tid >> 4, tx = tid & 15;
    float run_m[4], run_l[4];
    ull accP1[2][4], accP2[2][4];
#pragma unroll
    for (int i = 0; i < 4; i++) { run_m[i] = -1e30f; run_l[i] = 0.f; }
#pragma unroll
    for (int ip = 0; ip < 2; ip++)
#pragma unroll
        for (int jp = 0; jp < 4; jp++) { accP1[ip][jp] = 0ull; accP2[ip][jp] = 0ull; }

    for (int mt = (n0 >> 6); mt < NN / 64; ++mt) {
        int m0 = mt * 64;
        __syncthreads();
        for (int idx = tid; idx < 64 * 32; idx += 256) {
            int r = idx >> 5, c = (idx & 31) * 4;
            float4 kv = *(const float4*)&g_k[base + (size_t)(m0 + r) * 128 + c];
            Ks[(c + 0) * 64 + r] = kv.x;
            Ks[(c + 1) * 64 + r] = kv.y;
            Ks[(c + 2) * 64 + r] = kv.z;
            Ks[(c + 3) * 64 + r] = kv.w;
            float4 vv = *(const float4*)&g_v[base + (size_t)(m0 + r) * 128 + c];
            *(float4*)&Vs[r * 128 + c] = vv;
        }
        if (tid < 64) vm[tid] = (ids[b * NN + m0 + tid] != 0);
        __syncthreads();

        ull s1p[2][2], s2p[2][2];
#pragma unroll
        for (int i = 0; i < 2; i++)
#pragma unroll
            for (int j = 0; j < 2; j++) { s1p[i][j] = 0ull; s2p[i][j] = 0ull; }
#pragma unroll 4
        for (int kk = 0; kk < 128; kk++) {
            ulonglong2 qa = *(const ulonglong2*)&Qs[kk * 64 + ty * 4];
            ulonglong2 kb = *(const ulonglong2*)&Ks[kk * 64 + tx * 4];
            ull ap0 = qa.x, ap1 = qa.y;
            ull bp0 = kb.x, bp1 = kb.y;
            ull as0 = sw2(ap0), as1 = sw2(ap1);
            fma2(s1p[0][0], ap0, bp0); fma2(s1p[0][1], ap0, bp1);
            fma2(s1p[1][0], ap1, bp0); fma2(s1p[1][1], ap1, bp1);
            fma2(s2p[0][0], as0, bp0); fma2(s2p[0][1], as0, bp1);
            fma2(s2p[1][0], as1, bp0); fma2(s2p[1][1], as1, bp1);
        }
        float s[4][4];
#pragma unroll
        for (int ip = 0; ip < 2; ip++)
#pragma unroll
            for (int jp = 0; jp < 2; jp++) {
                float2 u1 = upk2(s1p[ip][jp]);
                float2 u2 = upk2(s2p[ip][jp]);
                s[2*ip  ][2*jp  ] = u1.x;
                s[2*ip+1][2*jp+1] = u1.y;
                s[2*ip+1][2*jp  ] = u2.x;
                s[2*ip  ][2*jp+1] = u2.y;
            }

        float resc[4];
#pragma unroll
        for (int i = 0; i < 4; i++) {
            int n = n0 + ty * 4 + i;
            int validn = vn[ty * 4 + i];
            float lg[4]; bool cnd[4];
            float tmax = -1e30f;
#pragma unroll
            for (int j = 0; j < 4; j++) {
                int m = m0 + tx * 4 + j;
                bool cc = (m > n) && validn && vm[tx * 4 + j];
                cnd[j] = cc;
                float sc = s[i][j];
                float l = cc ? (sc / (1.f + __expf(-sc))) * INV_N : -1e30f;
                lg[j] = l;
                tmax = fmaxf(tmax, l);
            }
#pragma unroll
            for (int o = 8; o > 0; o >>= 1)
                tmax = fmaxf(tmax, __shfl_xor_sync(0xffffffffu, tmax, o, 16));
            float newm = fmaxf(run_m[i], tmax);
            resc[i] = __expf(run_m[i] - newm);
            run_m[i] = newm;
            float p[4]; float psum = 0.f;
#pragma unroll
            for (int j = 0; j < 4; j++) {
                p[j] = cnd[j] ? __expf(lg[j] - newm) : 0.f;
                psum += p[j];
            }
#pragma unroll
            for (int o = 8; o > 0; o >>= 1)
                psum += __shfl_xor_sync(0xffffffffu, psum, o, 16);
            run_l[i] = run_l[i] * resc[i] + psum;
#pragma unroll
            for (int j = 0; j < 4; j++) Ps[(tx * 4 + j) * 64 + ty * 4 + i] = p[j];
        }
        {
            ull r1p[2] = {pk2(resc[0], resc[1]), pk2(resc[2], resc[3])};
            ull r2p[2] = {pk2(resc[1], resc[0]), pk2(resc[3], resc[2])};
#pragma unroll
            for (int ip = 0; ip < 2; ip++)
#pragma unroll
                for (int jp = 0; jp < 4; jp++) {
                    accP1[ip][jp] = mul2(accP1[ip][jp], r1p[ip]);
                    accP2[ip][jp] = mul2(accP2[ip][jp], r2p[ip]);
                }
        }
        __syncthreads();

#pragma unroll 2
        for (int mm = 0; mm < 64; mm++) {
            ulonglong2 pa = *(const ulonglong2*)&Ps[mm * 64 + ty * 4];
            ulonglong2 v0 = *(const ulonglong2*)&Vs[mm * 128 + tx * 8];
            ulonglong2 v1 = *(const ulonglong2*)&Vs[mm * 128 + tx * 8 + 4];
            ull pp0 = pa.x, pp1 = pa.y;
            ull ps0 = sw2(pp0), ps1 = sw2(pp1);
            ull vp[4] = {v0.x, v0.y, v1.x, v1.y};
#pragma unroll
            for (int jp = 0; jp < 4; jp++) {
                fma2(accP1[0][jp], pp0, vp[jp]);
                fma2(accP2[0][jp], ps0, vp[jp]);
                fma2(accP1[1][jp], pp1, vp[jp]);
                fma2(accP2[1][jp], ps1, vp[jp]);
            }
        }
    }

    float oacc[4][8];
#pragma unroll
    for (int ip = 0; ip < 2; ip++)
#pragma unroll
        for (int jp = 0; jp < 4; jp++) {
            float2 u1 = upk2(accP1[ip][jp]);
            float2 u2 = upk2(accP2[ip][jp]);
            oacc[2*ip  ][2*jp  ] = u1.x;
            oacc[2*ip+1][2*jp+1] = u1.y;
            oacc[2*ip+1][2*jp  ] = u2.x;
            oacc[2*ip  ][2*jp+1] = u2.y;
        }

#pragma unroll
    for (int i = 0; i < 4; i++) {
        int n = n0 + ty * 4 + i;
        size_t o = ((size_t)(b * NN + n)) * DD + h * 128 + tx * 8;
        float val[8];
        if (run_l[i] > 0.f) {
            float inv = 1.f / run_l[i];
#pragma unroll
            for (int j = 0; j < 8; j++) val[j] = oacc[i][j] * inv;
        } else {
            const float* mvp = g_mv + (b * HH + h) * 128 + tx * 8;
#pragma unroll
            for (int j = 0; j < 8; j++) val[j] = mvp[j];
        }
        bf16 hh[8], ll[8];
#pragma unroll
        for (int j = 0; j < 8; j++) split2(val[j], hh[j], ll[j]);
        ushort4 h0 = {us(hh[0]), us(hh[1]), us(hh[2]), us(hh[3])};
        ushort4 h1 = {us(hh[4]), us(hh[5]), us(hh[6]), us(hh[7])};
        ushort4 l0 = {us(ll[0]), us(ll[1]), us(ll[2]), us(ll[3])};
        ushort4 l1 = {us(ll[4]), us(ll[5]), us(ll[6]), us(ll[7])};
        *(ushort4*)&g_ath[o]     = h0;
        *(ushort4*)&g_ath[o + 4] = h1;
        *(ushort4*)&g_atl[o]     = l0;
        *(ushort4*)&g_atl[o + 4] = l1;
    }
}

// ---------------- launch ----------------
extern "C" void kernel_launch(void* const* d_in, const int* in_sizes, int n_in,
                              void* d_out, int out_size) {
    const int*   ids  = (const int*)d_in[1];     // past_ids (B,N)
    const float* emb  = (const float*)d_in[2];   // past_embeddings (B,N,D)
    const float* qkvw = (const float*)d_in[3];   // (4,1024,4096)
    const float* qkvb = (const float*)d_in[4];   // (4,4096)
    const float* outw = (const float*)d_in[5];   // (4,1024,1024)
    const float* outb = (const float*)d_in[6];   // (4,1024)
    const float* lng  = (const float*)d_in[7];   // (4,1024)
    const float* lnb  = (const float*)d_in[8];   // (4,1024)
    float* X = (float*)d_out;

    cudaFuncSetAttribute(attn_kernel,
                         cudaFuncAttributeMaxDynamicSharedMemorySize, ATTN_SMEM);
    cudaFuncSetAttribute(hmma_gemm,
                         cudaFuncAttributeMaxDynamicSharedMemorySize, HM_SMEM);

    cudaMemcpyAsync(X, emb, sizeof(float) * (size_t)MM * DD,
                    cudaMemcpyDeviceToDevice);

    // weight conversion (transpose + bf16 split), all layers
    wq_cvt<<<dim3(32, 96, NBLK), dim3(32, 8)>>>(qkvw);
    w2_cvt<<<dim3(32, 32, NBLK), dim3(32, 8)>>>(outw);

    for (int l = 0; l < NBLK; l++) {
        ln_kernel<<<MM, 256>>>(X, lng + l * DD, lnb + l * DD);
        hmma_gemm<<<dim3(24, 64), 256, HM_SMEM>>>(0, l, qkvb + (size_t)l * QKVW, X);
        meanv_kernel<<<BB * HH, 128>>>();
        attn_kernel<<<dim3(NN / 64, HH, BB), 256, ATTN_SMEM>>>(ids);
        hmma_gemm<<<dim3(8, 64), 256, HM_SMEM>>>(1, l, outb + (size_t)l * DD, X);
    }
}

// round 10
// speedup vs baseline: 2.5943x; 1.7760x over previous
#include <cuda_runtime.h>
#include <cuda_bf16.h>
#include <math.h>
#include <stdint.h>

#define BB 4
#define NN 2048
#define DD 1024
#define HH 8
#define NBLK 4
#define MM (BB*NN)          // 8192 rows
#define QKVW 4096
#define QSCALE 0.08838834764831845f   // 1/sqrt(128)
#define INV_N (1.0f/2048.0f)

typedef __nv_bfloat16 bf16;

// ---------------- scratch (device globals; no allocation allowed) ----------
__device__ bf16  g_xnh[MM*DD];           // ln output hi
__device__ bf16  g_xnl[MM*DD];           // ln output lo
__device__ bf16  g_qh[BB*HH*NN*128];     // q (scaled) hi   [b,h,n,d]
__device__ bf16  g_ql[BB*HH*NN*128];
__device__ bf16  g_kh[BB*HH*NN*128];
__device__ bf16  g_kl[BB*HH*NN*128];
__device__ bf16  g_vh[BB*HH*NN*128];
__device__ bf16  g_vl[BB*HH*NN*128];
__device__ bf16  g_ath[MM*DD];           // attn output hi
__device__ bf16  g_atl[MM*DD];           // attn output lo
__device__ float g_mv [BB*HH*128];       // fallback: column-mean of V per (b,h)
__device__ bf16  g_wqh[(size_t)NBLK*3072*DD];  // qkv W^T hi  [l][n(3072)][k(1024)]
__device__ bf16  g_wql[(size_t)NBLK*3072*DD];
__device__ bf16  g_w2h[(size_t)NBLK*DD*DD];    // out W^T hi  [l][n(1024)][k(1024)]
__device__ bf16  g_w2l[(size_t)NBLK*DD*DD];

// ---------------- small helpers ----------------
__device__ __forceinline__ void split2(float x, bf16 &h, bf16 &l) {
    h = __float2bfloat16(x);
    l = __float2bfloat16(x - __bfloat162float(h));
}
__device__ __forceinline__ unsigned short us(bf16 h) { return __bfloat16_as_ushort(h); }
__device__ __forceinline__ uint32_t pkbf(bf16 lo, bf16 hi) {
    return ((uint32_t)us(hi) << 16) | us(lo);
}

// ---------------- HMMA path: mma.sync + ldmatrix + cp.async ---------------
__device__ __forceinline__ uint32_t smem_u32(const void* p) {
    uint32_t a;
    asm("{ .reg .u64 t; cvta.to.shared.u64 t, %1; cvt.u32.u64 %0, t; }"
        : "=r"(a) : "l"(p));
    return a;
}
__device__ __forceinline__ void mma_bf16(float* c, const uint32_t* a, const uint32_t* b) {
    asm volatile(
        "mma.sync.aligned.m16n8k16.row.col.f32.bf16.bf16.f32 "
        "{%0,%1,%2,%3}, {%4,%5,%6,%7}, {%8,%9}, {%0,%1,%2,%3};"
        : "+f"(c[0]), "+f"(c[1]), "+f"(c[2]), "+f"(c[3])
        : "r"(a[0]), "r"(a[1]), "r"(a[2]), "r"(a[3]), "r"(b[0]), "r"(b[1]));
}
__device__ __forceinline__ void ldsm4(uint32_t* r, uint32_t addr) {
    asm volatile("ldmatrix.sync.aligned.m8n8.x4.shared.b16 {%0,%1,%2,%3}, [%4];"
                 : "=r"(r[0]), "=r"(r[1]), "=r"(r[2]), "=r"(r[3]) : "r"(addr));
}
__device__ __forceinline__ void ldsm4t(uint32_t* r, uint32_t addr) {
    asm volatile("ldmatrix.sync.aligned.m8n8.x4.trans.shared.b16 {%0,%1,%2,%3}, [%4];"
                 : "=r"(r[0]), "=r"(r[1]), "=r"(r[2]), "=r"(r[3]) : "r"(addr));
}
__device__ __forceinline__ void cpa16(uint32_t dst, const void* src) {
    asm volatile("cp.async.ca.shared.global [%0], [%1], 16;"
                 :: "r"(dst), "l"(src) : "memory");
}
#define CPA_COMMIT asm volatile("cp.async.commit_group;" ::: "memory")
#define CPA_WAIT1  asm volatile("cp.async.wait_group 1;" ::: "memory")
#define CPA_WAIT0  asm volatile("cp.async.wait_group 0;" ::: "memory")

// ---------------- LayerNorm: one row per block, emits bf16 hi/lo ----------
__global__ void ln_kernel(const float* __restrict__ x,
                          const float* __restrict__ g,
                          const float* __restrict__ bta) {
    __shared__ float sh[8];
    __shared__ float bc[2];
    int row = blockIdx.x;
    int tid = threadIdx.x;
    int lane = tid & 31, wid = tid >> 5;

    const float4* xr = (const float4*)(x + (size_t)row * DD);
    float4 v = xr[tid];

    float s = v.x + v.y + v.z + v.w;
#pragma unroll
    for (int o = 16; o > 0; o >>= 1) s += __shfl_xor_sync(0xffffffffu, s, o);
    if (lane == 0) sh[wid] = s;
    __syncthreads();
    if (tid == 0) {
        float t = 0.f;
#pragma unroll
        for (int i = 0; i < 8; i++) t += sh[i];
        bc[0] = t;
    }
    __syncthreads();
    float mu = bc[0] * (1.f / DD);

    float dx = v.x - mu, dy = v.y - mu, dz = v.z - mu, dw = v.w - mu;

    float sq = dx*dx + dy*dy + dz*dz + dw*dw;
#pragma unroll
    for (int o = 16; o > 0; o >>= 1) sq += __shfl_xor_sync(0xffffffffu, sq, o);
    if (lane == 0) sh[wid] = sq;
    __syncthreads();
    if (tid == 0) {
        float t = 0.f;
#pragma unroll
        for (int i = 0; i < 8; i++) t += sh[i];
        bc[1] = t;
    }
    __syncthreads();
    float rs = rsqrtf(bc[1] * (1.f / DD) + 1e-5f);

    float4 gg = ((const float4*)g)[tid];
    float4 bb = ((const float4*)bta)[tid];
    float o0 = dx * rs * gg.x + bb.x;
    float o1 = dy * rs * gg.y + bb.y;
    float o2 = dz * rs * gg.z + bb.z;
    float o3 = dw * rs * gg.w + bb.w;

    bf16 h0, h1, h2, h3, l0, l1, l2, l3;
    split2(o0, h0, l0); split2(o1, h1, l1);
    split2(o2, h2, l2); split2(o3, h3, l3);
    size_t o = (size_t)row * DD + tid * 4;
    ushort4 hv = {us(h0), us(h1), us(h2), us(h3)};
    ushort4 lv = {us(l0), us(l1), us(l2), us(l3)};
    *(ushort4*)&g_xnh[o] = hv;
    *(ushort4*)&g_xnl[o] = lv;
}

// ---------------- weight transpose + split (once per launch) ---------------
__global__ void wq_cvt(const float* __restrict__ qkvw) {
    __shared__ float t[32][33];
    int l = blockIdx.z;
    int k0 = blockIdx.x * 32, n0 = blockIdx.y * 32;
    int chunk = n0 >> 7, head = chunk / 3, part = chunk % 3;
    int wbase = head * 512 + part * 128 + (n0 & 127);
    const float* W = qkvw + (size_t)l * DD * QKVW;
#pragma unroll
    for (int s = 0; s < 4; s++)
        t[threadIdx.y + 8*s][threadIdx.x] =
            W[(size_t)(k0 + threadIdx.y + 8*s) * QKVW + wbase + threadIdx.x];
    __syncthreads();
#pragma unroll
    for (int s = 0; s < 4; s++) {
        int n = n0 + threadIdx.y + 8*s;
        float v = t[threadIdx.x][threadIdx.y + 8*s];
        bf16 h, lo; split2(v, h, lo);
        size_t o = ((size_t)l * 3072 + n) * DD + k0 + threadIdx.x;
        g_wqh[o] = h; g_wql[o] = lo;
    }
}
__global__ void w2_cvt(const float* __restrict__ outw) {
    __shared__ float t[32][33];
    int l = blockIdx.z;
    int k0 = blockIdx.x * 32, n0 = blockIdx.y * 32;
    const float* W = outw + (size_t)l * DD * DD;
#pragma unroll
    for (int s = 0; s < 4; s++)
        t[threadIdx.y + 8*s][threadIdx.x] =
            W[(size_t)(k0 + threadIdx.y + 8*s) * DD + n0 + threadIdx.x];
    __syncthreads();
#pragma unroll
    for (int s = 0; s < 4; s++) {
        int n = n0 + threadIdx.y + 8*s;
        float v = t[threadIdx.x][threadIdx.y + 8*s];
        bf16 h, lo; split2(v, h, lo);
        size_t o = ((size_t)l * DD + n) * DD + k0 + threadIdx.x;
        g_w2h[o] = h; g_w2l[o] = lo;
    }
}

// ---------------- HMMA GEMM: 128x128 tile, BK=32, split-bf16 (3 MMAs) -----
// mode 0: C = xn @ Wqkv + bias -> split bf16 q(scaled)/k/v   (grid (24, 64))
// mode 1: X += attn @ Wout + bias                            (grid (8, 64))
#define RSTR 80
#define ST_A_H 0
#define ST_A_L 10240
#define ST_B_H 20480
#define ST_B_L 30720
#define STAGE  40960
#define HM_SMEM (2*STAGE)

__global__ __launch_bounds__(256) void hmma_gemm(int mode, int layer,
                                                 const float* __restrict__ bias,
                                                 float* __restrict__ X) {
    extern __shared__ char smem[];
    uint32_t sb = smem_u32(smem);
    int tid = threadIdx.x;
    int w = tid >> 5, lane = tid & 31;
    int row0 = blockIdx.y * 128;
    int bx = blockIdx.x;

    const bf16* Ah = ((mode == 0) ? g_xnh : g_ath) + (size_t)row0 * DD;
    const bf16* Al = ((mode == 0) ? g_xnl : g_atl) + (size_t)row0 * DD;
    const bf16* Bh = ((mode == 0) ? (g_wqh + (size_t)layer * 3072 * DD)
                                  : (g_w2h + (size_t)layer * DD * DD))
                     + (size_t)(bx * 128) * DD;
    const bf16* Bl = ((mode == 0) ? (g_wql + (size_t)layer * 3072 * DD)
                                  : (g_w2l + (size_t)layer * DD * DD))
                     + (size_t)(bx * 128) * DD;

    float c[4][4][4];
#pragma unroll
    for (int i = 0; i < 4; i++)
#pragma unroll
        for (int j = 0; j < 4; j++)
#pragma unroll
            for (int q = 0; q < 4; q++) c[i][j][q] = 0.f;

    int wm = w & 1, wn = w >> 1;
    int grp = lane >> 3, r8 = lane & 7;
    int arow = wm * 64 + (grp & 1) * 8 + r8;
    int akb0 = (grp >> 1) * 16;
    int brow = wn * 32 + (grp >> 1) * 8 + r8;
    int bkb0 = (grp & 1) * 16;

    {
        uint32_t s0 = sb;
#pragma unroll
        for (int ch = tid; ch < 512; ch += 256) {
            int row = ch >> 2, cw = ch & 3;
            uint32_t so = row * RSTR + cw * 16;
            size_t go = (size_t)row * DD + cw * 8;
            cpa16(s0 + ST_A_H + so, (const char*)(Ah + go));
            cpa16(s0 + ST_A_L + so, (const char*)(Al + go));
            cpa16(s0 + ST_B_H + so, (const char*)(Bh + go));
            cpa16(s0 + ST_B_L + so, (const char*)(Bl + go));
        }
        CPA_COMMIT;
    }

    for (int s = 0; s < 32; s++) {
        if (s + 1 < 32) {
            uint32_t s0 = sb + ((s + 1) & 1) * STAGE;
            int k0 = (s + 1) * 32;
#pragma unroll
            for (int ch = tid; ch < 512; ch += 256) {
                int row = ch >> 2, cw = ch & 3;
                uint32_t so = row * RSTR + cw * 16;
                size_t go = (size_t)row * DD + k0 + cw * 8;
                cpa16(s0 + ST_A_H + so, (const char*)(Ah + go));
                cpa16(s0 + ST_A_L + so, (const char*)(Al + go));
                cpa16(s0 + ST_B_H + so, (const char*)(Bh + go));
                cpa16(s0 + ST_B_L + so, (const char*)(Bl + go));
            }
        }
        CPA_COMMIT;
        CPA_WAIT1;
        __syncthreads();
        uint32_t base = sb + (s & 1) * STAGE;
#pragma unroll
        for (int k16 = 0; k16 < 2; k16++) {
            uint32_t ah[4][4], al[4][4], bh[2][4], bl[2][4];
            int akb = k16 * 32 + akb0;
            int bkb = k16 * 32 + bkb0;
#pragma unroll
            for (int i = 0; i < 4; i++) {
                uint32_t ao = (uint32_t)(arow + i * 16) * RSTR + akb;
                ldsm4(ah[i], base + ST_A_H + ao);
                ldsm4(al[i], base + ST_A_L + ao);
            }
#pragma unroll
            for (int j = 0; j < 2; j++) {
                uint32_t bo = (uint32_t)(brow + j * 16) * RSTR + bkb;
                ldsm4(bh[j], base + ST_B_H + bo);
                ldsm4(bl[j], base + ST_B_L + bo);
            }
#pragma unroll
            for (int i = 0; i < 4; i++)
#pragma unroll
                for (int jn = 0; jn < 4; jn++) {
                    const uint32_t* bph = &bh[jn >> 1][(jn & 1) * 2];
                    const uint32_t* bpl = &bl[jn >> 1][(jn & 1) * 2];
                    mma_bf16(c[i][jn], ah[i], bph);
                    mma_bf16(c[i][jn], ah[i], bpl);
                    mma_bf16(c[i][jn], al[i], bph);
                }
        }
        __syncthreads();
    }
    CPA_WAIT0;

    int quad = lane >> 2, tq = lane & 3;
    if (mode == 0) {
        int head = bx / 3, part = bx % 3;
        int wcol0 = head * 512 + part * 128;
        bf16* dh = (part == 0) ? g_qh : (part == 1) ? g_kh : g_vh;
        bf16* dl = (part == 0) ? g_ql : (part == 1) ? g_kl : g_vl;
        float scale = (part == 0) ? QSCALE : 1.f;
#pragma unroll
        for (int i = 0; i < 4; i++)
#pragma unroll
            for (int half = 0; half < 2; half++) {
                int r = row0 + wm * 64 + i * 16 + quad + half * 8;
                int b = r >> 11, n = r & (NN - 1);
                size_t ro = ((size_t)(b * HH + head) * NN + n) * 128;
#pragma unroll
                for (int jn = 0; jn < 4; jn++) {
                    int col = wn * 32 + jn * 8 + tq * 2;
                    float x0 = (c[i][jn][half*2+0] + bias[wcol0 + col]) * scale;
                    float x1 = (c[i][jn][half*2+1] + bias[wcol0 + col + 1]) * scale;
                    bf16 h0, l0, h1, l1;
                    split2(x0, h0, l0); split2(x1, h1, l1);
                    ushort2 hv = {us(h0), us(h1)};
                    ushort2 lv = {us(l0), us(l1)};
                    *(ushort2*)&dh[ro + col] = hv;
                    *(ushort2*)&dl[ro + col] = lv;
                }
            }
    } else {
        int col0 = bx * 128;
#pragma unroll
        for (int i = 0; i < 4; i++)
#pragma unroll
            for (int half = 0; half < 2; half++) {
                size_t r = row0 + wm * 64 + i * 16 + quad + half * 8;
#pragma unroll
                for (int jn = 0; jn < 4; jn++) {
                    int col = col0 + wn * 32 + jn * 8 + tq * 2;
                    float2 x = *(float2*)&X[r * DD + col];
                    x.x += c[i][jn][half*2+0] + bias[col];
                    x.y += c[i][jn][half*2+1] + bias[col + 1];
                    *(float2*)&X[r * DD + col] = x;
                }
            }
    }
}

// ---------------- meanV: fallback for fully-masked rows -------------------
__global__ void meanv_kernel() {
    int bh = blockIdx.x;
    int d = threadIdx.x;
    const bf16* vh = g_vh + (size_t)bh * NN * 128 + d;
    const bf16* vl = g_vl + (size_t)bh * NN * 128 + d;
    float s0 = 0.f, s1 = 0.f;
    for (int m = 0; m < NN; m += 2) {
        s0 += __bfloat162float(vh[(size_t)m * 128]) + __bfloat162float(vl[(size_t)m * 128]);
        s1 += __bfloat162float(vh[(size_t)(m+1) * 128]) + __bfloat162float(vl[(size_t)(m+1) * 128]);
    }
    g_mv[bh * 128 + d] = (s0 + s1) * INV_N;
}

// ---------------- attention: HMMA flash, 128-q CTA, 64-key tiles ----------
// smem: 2 stages of {Kh,Kl,Vh,Vl}[64][136bf16] + flags. Q staged temporarily.
#define AT_PITCH 272
#define AT_KH 0
#define AT_KL 17408
#define AT_VH 34816
#define AT_VL 52224
#define AT_STAGE 69632
#define AT_FLAGS (2*AT_STAGE)
#define ATTN_SMEM (AT_FLAGS + 512 + 512)

__global__ __launch_bounds__(256) void attn_kernel(const int* __restrict__ ids) {
    extern __shared__ char smem[];
    uint32_t sb = smem_u32(smem);
    int* vn  = (int*)(smem + AT_FLAGS);
    int* vmb = (int*)(smem + AT_FLAGS + 512);

    int tid = threadIdx.x;
    int w = tid >> 5, lane = tid & 31;
    int quad = lane >> 2, tq = lane & 3;
    int grp = lane >> 3, r8 = lane & 7;
    int n0 = blockIdx.x * 128;
    int h = blockIdx.y, b = blockIdx.z;
    size_t base = (size_t)(b * HH + h) * NN * 128;   // elem offset in [n][d]

    // ---- stage Q (hi at stage0, lo at stage1), pull fragments to regs ----
    {
        const char* ph = (const char*)(g_qh + base + (size_t)n0 * 128);
        const char* pl = (const char*)(g_ql + base + (size_t)n0 * 128);
        for (int ch = tid; ch < 2048; ch += 256) {
            int row = ch >> 4, c = ch & 15;
            cpa16(sb + row * AT_PITCH + c * 16, ph + row * 256 + c * 16);
            cpa16(sb + AT_STAGE + row * AT_PITCH + c * 16, pl + row * 256 + c * 16);
        }
        CPA_COMMIT; CPA_WAIT0;
    }
    if (tid < 128) vn[tid] = (ids[b * NN + n0 + tid] != 0);
    __syncthreads();

    uint32_t qfh[8][4], qfl[8][4];
    {
        int arow = w * 16 + (grp & 1) * 8 + r8;
#pragma unroll
        for (int kt = 0; kt < 8; kt++) {
            uint32_t ao = (uint32_t)arow * AT_PITCH + kt * 32 + (grp >> 1) * 16;
            ldsm4(qfh[kt], sb + ao);
            ldsm4(qfl[kt], sb + AT_STAGE + ao);
        }
    }
    __syncthreads();   // Q staging area now reusable as K/V stages

    float o[16][4];
#pragma unroll
    for (int dt = 0; dt < 16; dt++)
#pragma unroll
        for (int q = 0; q < 4; q++) o[dt][q] = 0.f;
    float run_m[2] = {-1e30f, -1e30f}, run_l[2] = {0.f, 0.f};

    const char* kh = (const char*)(g_kh + base);
    const char* kl = (const char*)(g_kl + base);
    const char* vh = (const char*)(g_vh + base);
    const char* vl = (const char*)(g_vl + base);

    int mt0 = n0 >> 6;
    auto prefetch = [&](int mt, int st) {
        int m0 = mt * 64;
        uint32_t s0 = sb + st * AT_STAGE;
        for (int ch = tid; ch < 1024; ch += 256) {
            int row = ch >> 4, c = ch & 15;
            uint32_t so = row * AT_PITCH + c * 16;
            size_t go = (size_t)(m0 + row) * 256 + c * 16;
            cpa16(s0 + AT_KH + so, kh + go);
            cpa16(s0 + AT_KL + so, kl + go);
            cpa16(s0 + AT_VH + so, vh + go);
            cpa16(s0 + AT_VL + so, vl + go);
        }
        if (tid < 64) vmb[st * 64 + tid] = (ids[b * NN + m0 + tid] != 0);
        CPA_COMMIT;
    };
    prefetch(mt0, 0);

    for (int mt = mt0; mt < NN / 64; mt++) {
        int st = (mt - mt0) & 1;
        if (mt + 1 < NN / 64) { prefetch(mt + 1, st ^ 1); CPA_WAIT1; }
        else                  { CPA_WAIT0; }
        __syncthreads();

        uint32_t stb = sb + st * AT_STAGE;
        int m0 = mt * 64;
        const int* vm = vmb + st * 64;

        // ---- S = Q K^T (16 rows x 64 keys per warp) ----
        float s[8][4];
#pragma unroll
        for (int nt = 0; nt < 8; nt++)
#pragma unroll
            for (int q = 0; q < 4; q++) s[nt][q] = 0.f;
#pragma unroll
        for (int kt = 0; kt < 8; kt++) {
            uint32_t bh[4][4], bl[4][4];
#pragma unroll
            for (int ng = 0; ng < 4; ng++) {
                uint32_t ro = (uint32_t)(ng * 16 + (grp >> 1) * 8 + r8) * AT_PITCH
                            + kt * 32 + (grp & 1) * 16;
                ldsm4(bh[ng], stb + AT_KH + ro);
                ldsm4(bl[ng], stb + AT_KL + ro);
            }
#pragma unroll
            for (int ng = 0; ng < 4; ng++)
#pragma unroll
                for (int hf = 0; hf < 2; hf++) {
                    int nt = ng * 2 + hf;
                    const uint32_t* bph = &bh[ng][hf * 2];
                    const uint32_t* bpl = &bl[ng][hf * 2];
                    mma_bf16(s[nt], qfh[kt], bph);
                    mma_bf16(s[nt], qfh[kt], bpl);
                    mma_bf16(s[nt], qfl[kt], bph);
                }
        }

        // ---- masked silu + online softmax (row owned by 4 lanes) ----
        float resc[2];
#pragma unroll
        for (int hf = 0; hf < 2; hf++) {
            int rloc = w * 16 + quad + hf * 8;
            int n = n0 + rloc;
            int validn = vn[rloc];
            float lg[16]; bool cnd[16];
            float tmax = -1e30f;
#pragma unroll
            for (int nt = 0; nt < 8; nt++)
#pragma unroll
                for (int c2 = 0; c2 < 2; c2++) {
                    int mloc = nt * 8 + tq * 2 + c2;
                    int m = m0 + mloc;
                    bool cc = (m > n) && validn && vm[mloc];
                    float sc = s[nt][hf * 2 + c2];
                    float l = cc ? (sc / (1.f + __expf(-sc))) * INV_N : -1e30f;
                    cnd[nt * 2 + c2] = cc;
                    lg[nt * 2 + c2] = l;
                    tmax = fmaxf(tmax, l);
                }
            tmax = fmaxf(tmax, __shfl_xor_sync(0xffffffffu, tmax, 1));
            tmax = fmaxf(tmax, __shfl_xor_sync(0xffffffffu, tmax, 2));
            float newm = fmaxf(run_m[hf], tmax);
            resc[hf] = __expf(run_m[hf] - newm);
            run_m[hf] = newm;
            float psum = 0.f;
#pragma unroll
            for (int nt = 0; nt < 8; nt++)
#pragma unroll
                for (int c2 = 0; c2 < 2; c2++) {
                    float p = cnd[nt * 2 + c2] ? __expf(lg[nt * 2 + c2] - newm) : 0.f;
                    s[nt][hf * 2 + c2] = p;
                    psum += p;
                }
            psum += __shfl_xor_sync(0xffffffffu, psum, 1);
            psum += __shfl_xor_sync(0xffffffffu, psum, 2);
            run_l[hf] = run_l[hf] * resc[hf] + psum;
        }
#pragma unroll
        for (int dt = 0; dt < 16; dt++) {
            o[dt][0] *= resc[0]; o[dt][1] *= resc[0];
            o[dt][2] *= resc[1]; o[dt][3] *= resc[1];
        }

        // ---- O += P V (P split hi/lo in regs; V via ldmatrix.trans) ----
#pragma unroll
        for (int kv = 0; kv < 4; kv++) {
            uint32_t ph[4], pl[4];
#pragma unroll
            for (int half = 0; half < 2; half++) {   // a0,a1 from nt=2kv; a2,a3 from 2kv+1
                int nt = kv * 2 + half;
                bf16 h0, l0, h1, l1, h2, l2, h3, l3;
                split2(s[nt][0], h0, l0); split2(s[nt][1], h1, l1);
                split2(s[nt][2], h2, l2); split2(s[nt][3], h3, l3);
                ph[half * 2 + 0] = pkbf(h0, h1);  pl[half * 2 + 0] = pkbf(l0, l1);
                ph[half * 2 + 1] = pkbf(h2, h3);  pl[half * 2 + 1] = pkbf(l2, l3);
            }
            // reorder: a0=(row q, k0-7)=ph[0], a1=(row q+8,k0-7)=ph[1],
            //          a2=(row q, k8-15)=ph[2], a3=ph[3]  -- already in order
#pragma unroll
            for (int dg = 0; dg < 8; dg++) {
                uint32_t vfh[4], vfl[4];
                uint32_t ro = (uint32_t)(kv * 16 + (grp & 1) * 8 + r8) * AT_PITCH
                            + dg * 32 + (grp >> 1) * 16;
                ldsm4t(vfh, stb + AT_VH + ro);
                ldsm4t(vfl, stb + AT_VL + ro);
#pragma unroll
                for (int hf = 0; hf < 2; hf++) {
                    int dt = dg * 2 + hf;
                    const uint32_t* bph = &vfh[hf * 2];
                    const uint32_t* bpl = &vfl[hf * 2];
                    mma_bf16(o[dt], ph, bph);
                    mma_bf16(o[dt], ph, bpl);
                    mma_bf16(o[dt], pl, bph);
                }
            }
        }
        __syncthreads();
    }

    // ---- epilogue: normalize / fallback, write split bf16 ----
#pragma unroll
    for (int hf = 0; hf < 2; hf++) {
        int n = n0 + w * 16 + quad + hf * 8;
        size_t orow = (size_t)(b * NN + n) * DD + h * 128;
        bool fb = !(run_l[hf] > 0.f);
        float inv = fb ? 0.f : 1.f / run_l[hf];
        const float* mvp = g_mv + (b * HH + h) * 128;
#pragma unroll
        for (int dt = 0; dt < 16; dt++) {
            int d = dt * 8 + tq * 2;
            float x0, x1;
            if (fb) { x0 = mvp[d]; x1 = mvp[d + 1]; }
            else    { x0 = o[dt][hf * 2] * inv; x1 = o[dt][hf * 2 + 1] * inv; }
            bf16 h0, l0, h1, l1;
            split2(x0, h0, l0); split2(x1, h1, l1);
            ushort2 hv = {us(h0), us(h1)};
            ushort2 lv = {us(l0), us(l1)};
            *(ushort2*)&g_ath[orow + d] = hv;
            *(ushort2*)&g_atl[orow + d] = lv;
        }
    }
}

// ---------------- launch ----------------
extern "C" void kernel_launch(void* const* d_in, const int* in_sizes, int n_in,
                              void* d_out, int out_size) {
    const int*   ids  = (const int*)d_in[1];     // past_ids (B,N)
    const float* emb  = (const float*)d_in[2];   // past_embeddings (B,N,D)
    const float* qkvw = (const float*)d_in[3];   // (4,1024,4096)
    const float* qkvb = (const float*)d_in[4];   // (4,4096)
    const float* outw = (const float*)d_in[5];   // (4,1024,1024)
    const float* outb = (const float*)d_in[6];   // (4,1024)
    const float* lng  = (const float*)d_in[7];   // (4,1024)
    const float* lnb  = (const float*)d_in[8];   // (4,1024)
    float* X = (float*)d_out;

    cudaFuncSetAttribute(attn_kernel,
                         cudaFuncAttributeMaxDynamicSharedMemorySize, ATTN_SMEM);
    cudaFuncSetAttribute(hmma_gemm,
                         cudaFuncAttributeMaxDynamicSharedMemorySize, HM_SMEM);

    cudaMemcpyAsync(X, emb, sizeof(float) * (size_t)MM * DD,
                    cudaMemcpyDeviceToDevice);

    wq_cvt<<<dim3(32, 96, NBLK), dim3(32, 8)>>>(qkvw);
    w2_cvt<<<dim3(32, 32, NBLK), dim3(32, 8)>>>(outw);

    for (int l = 0; l < NBLK; l++) {
        ln_kernel<<<MM, 256>>>(X, lng + l * DD, lnb + l * DD);
        hmma_gemm<<<dim3(24, 64), 256, HM_SMEM>>>(0, l, qkvb + (size_t)l * QKVW, X);
        meanv_kernel<<<BB * HH, 128>>>();
        attn_kernel<<<dim3(NN / 128, HH, BB), 256, ATTN_SMEM>>>(ids);
        hmma_gemm<<<dim3(8, 64), 256, HM_SMEM>>>(1, l, outb + (size_t)l * DD, X);
    }
}